// round 12
// baseline (speedup 1.0000x reference)
#include <cuda_runtime.h>
#include <cuda_bf16.h>

// dLDS_continuous: out[b] = expm(sum_m c[b,m] * G[m]) @ x[b]
// B = 2097152, N = 3, M = 6.
//
// Cayley-Hamilton coefficient-space expm, packed f32x2, 2 batches/thread.
// R10 algorithm (folded-constant Horner deg-9 Taylor, s=3, early matvec,
// LDS.128 G loads) + R11 change: __launch_bounds__(256, 6) caps regs at 42
// (was 46) -> 6 blocks/SM = 48 warps = 75% theoretical occupancy (was 40/62.5%).
// Live set through Taylor/squaring is ~38 regs, so the cap should reschedule,
// not spill. out = a0*x + (a1/8)*y + (a2/64)*z.

static constexpr int B_TOTAL = 2097152;
static constexpr int THREADS = 256;

typedef unsigned long long u64;

__device__ __forceinline__ u64 pk(float a, float b) {
    u64 r; asm("mov.b64 %0, {%1,%2};" : "=l"(r) : "f"(a), "f"(b)); return r;
}
__device__ __forceinline__ void upk(u64 v, float& a, float& b) {
    asm("mov.b64 {%0,%1}, %2;" : "=f"(a), "=f"(b) : "l"(v));
}
__device__ __forceinline__ u64 f2fma(u64 a, u64 b, u64 c) {
    u64 r; asm("fma.rn.f32x2 %0, %1, %2, %3;" : "=l"(r) : "l"(a), "l"(b), "l"(c)); return r;
}
__device__ __forceinline__ u64 f2mul(u64 a, u64 b) {
    u64 r; asm("mul.rn.f32x2 %0, %1, %2;" : "=l"(r) : "l"(a), "l"(b)); return r;
}
__device__ __forceinline__ u64 f2add(u64 a, u64 b) {
    u64 r; asm("add.rn.f32x2 %0, %1, %2;" : "=l"(r) : "l"(a), "l"(b)); return r;
}
__device__ __forceinline__ u64 f2sub(u64 a, u64 b) {
    u64 r; asm("sub.rn.f32x2 %0, %1, %2;" : "=l"(r) : "l"(a), "l"(b)); return r;
}

__global__ void __launch_bounds__(THREADS, 6)
expm_apply_kernel(const float* __restrict__ x,
                  const float* __restrict__ c,
                  const float* __restrict__ G,
                  float* __restrict__ out)
{
    // rows padded to 10 u64: 16B-aligned pairs -> ld.shared.v2.u64
    __shared__ alignas(16) u64 sG[60];
    int tid = threadIdx.x;
    if (tid < 54) {
        int m = tid / 9, k = tid % 9;
        float g = G[tid];
        sG[m * 10 + k] = pk(g, g);
    }
    __syncthreads();

    unsigned t = blockIdx.x * THREADS + tid;   // pair index: batches 2t, 2t+1

    // ---- global loads issued up front ----
    const float4* c4 = reinterpret_cast<const float4*>(c) + t * 3u;
    float4 q0 = c4[0];
    float4 q1 = c4[1];
    float4 q2 = c4[2];
    const float2* x2 = reinterpret_cast<const float2*>(x) + t * 3u;
    float2 xa = x2[0];
    float2 xb = x2[1];
    float2 xc = x2[2];

    u64 X0, X1, X2, Y0, Y1, Y2, Z0, Z1, Z2;
    u64 c0i, c1i, c2i;
    {
        u64 cc[6] = { pk(q0.x, q1.z), pk(q0.y, q1.w), pk(q0.z, q2.x),
                      pk(q0.w, q2.y), pk(q1.x, q2.z), pk(q1.y, q2.w) };

        // ---- T = sum_m c[m]*G[m]; G rows via 4x LDS.128 + 1x LDS.64 ----
        u64 A[9];
#pragma unroll
        for (int m = 0; m < 6; ++m) {
            const u64* row = &sG[m * 10];
            u64 cm = cc[m];
#pragma unroll
            for (int kp = 0; kp < 4; ++kp) {
                ulonglong2 g2 = *reinterpret_cast<const ulonglong2*>(row + 2 * kp);
                if (m == 0) {
                    A[2 * kp]     = f2mul(cm, g2.x);
                    A[2 * kp + 1] = f2mul(cm, g2.y);
                } else {
                    A[2 * kp]     = f2fma(cm, g2.x, A[2 * kp]);
                    A[2 * kp + 1] = f2fma(cm, g2.y, A[2 * kp + 1]);
                }
            }
            u64 g8 = row[8];
            if (m == 0) A[8] = f2mul(cm, g8);
            else        A[8] = f2fma(cm, g8, A[8]);
        }

        // ---- invariants of T ----
        u64 I1 = f2add(f2add(A[0], A[4]), A[8]);
        u64 m0 = f2sub(f2mul(A[4], A[8]), f2mul(A[5], A[7]));
        u64 m1 = f2sub(f2mul(A[0], A[8]), f2mul(A[2], A[6]));
        u64 m2 = f2sub(f2mul(A[0], A[4]), f2mul(A[1], A[3]));
        u64 I2 = f2add(f2add(m0, m1), m2);
        u64 u1 = f2sub(f2mul(A[3], A[8]), f2mul(A[5], A[6]));
        u64 u2 = f2sub(f2mul(A[3], A[7]), f2mul(A[4], A[6]));
        u64 I3 = f2fma(A[0], m0, f2sub(f2mul(A[2], u2), f2mul(A[1], u1)));

        // char poly of As = T/8:  As^3 = c0 I + c1 As + c2 As^2  (s = 3)
        const u64 SC1  = pk( 1.f / 8.f,   1.f / 8.f);
        const u64 SC2N = pk(-1.f / 64.f, -1.f / 64.f);
        const u64 SC3  = pk( 1.f / 512.f, 1.f / 512.f);
        c2i = f2mul(I1, SC1);
        c1i = f2mul(I2, SC2N);
        c0i = f2mul(I3, SC3);

        // ---- early matvecs: y = T x, z = T y (A dies here) ----
        X0 = pk(xa.x, xb.y);
        X1 = pk(xa.y, xc.x);
        X2 = pk(xb.x, xc.y);
        Y0 = f2fma(A[0], X0, f2fma(A[1], X1, f2mul(A[2], X2)));
        Y1 = f2fma(A[3], X0, f2fma(A[4], X1, f2mul(A[5], X2)));
        Y2 = f2fma(A[6], X0, f2fma(A[7], X1, f2mul(A[8], X2)));
        Z0 = f2fma(A[0], Y0, f2fma(A[1], Y1, f2mul(A[2], Y2)));
        Z1 = f2fma(A[3], Y0, f2fma(A[4], Y1, f2mul(A[5], Y2)));
        Z2 = f2fma(A[6], Y0, f2fma(A[7], Y1, f2mul(A[8], Y2)));
    }

    // ---- Taylor deg 9, folded-constant Horner in triple space ----
    // W_j = As*W_{j+1} + (9!/j!) I ; after two trivial iters W = (72, 9, 1).
    u64 w0 = pk(72.f, 72.f);
    u64 w1 = pk(9.f, 9.f);
    u64 w2 = pk(1.f, 1.f);
    const float MJ[7] = { 504.f, 3024.f, 15120.f, 60480.f,
                          181440.f, 362880.f, 362880.f };  // 9!/j!, j=6..0
#pragma unroll
    for (int k = 0; k < 7; ++k) {
        u64 Mj = pk(MJ[k], MJ[k]);
        u64 nw0 = f2fma(w2, c0i, Mj);
        u64 nw1 = f2fma(w2, c1i, w0);
        u64 nw2 = f2fma(w2, c2i, w1);
        w0 = nw0; w1 = nw1; w2 = nw2;
    }
    // normalize: E = W / 9!
    const u64 NRM = pk(1.f / 362880.f, 1.f / 362880.f);
    u64 a0 = f2mul(w0, NRM);
    u64 a1 = f2mul(w1, NRM);
    u64 a2 = f2mul(w2, NRM);

    // ---- As^4 reduction triple ----
    u64 d0 = f2mul(c2i, c0i);
    u64 d1 = f2fma(c2i, c1i, c0i);
    u64 d2 = f2fma(c2i, c2i, c1i);

    // ---- 3 squarings in coefficient space (s = 3) ----
#pragma unroll
    for (int it = 0; it < 3; ++it) {
        u64 q01 = f2mul(a0, a1);
        u64 q02 = f2mul(a0, a2);
        u64 q12 = f2mul(a1, a2);
        u64 q22 = f2mul(a2, a2);
        u64 t12 = f2add(q12, q12);
        u64 b0 = f2fma(q22, d0, f2fma(t12, c0i, f2mul(a0, a0)));
        u64 b1 = f2fma(q22, d1, f2fma(t12, c1i, f2add(q01, q01)));
        u64 b2 = f2fma(q22, d2, f2fma(t12, c2i, f2fma(a1, a1, f2add(q02, q02))));
        a0 = b0; a1 = b1; a2 = b2;
    }
    // fold 2^-3 / 2^-6 (y, z were computed with raw T)
    a1 = f2mul(a1, pk(1.f / 8.f,  1.f / 8.f));
    a2 = f2mul(a2, pk(1.f / 64.f, 1.f / 64.f));

    // ---- out = a0*x + a1*y + a2*z ----
    u64 O0 = f2fma(a0, X0, f2fma(a1, Y0, f2mul(a2, Z0)));
    u64 O1 = f2fma(a0, X1, f2fma(a1, Y1, f2mul(a2, Z1)));
    u64 O2 = f2fma(a0, X2, f2fma(a1, Y2, f2mul(a2, Z2)));

    float o0l, o0h, o1l, o1h, o2l, o2h;
    upk(O0, o0l, o0h);
    upk(O1, o1l, o1h);
    upk(O2, o2l, o2h);

    float2* ob = reinterpret_cast<float2*>(out) + t * 3u;
    ob[0] = make_float2(o0l, o1l);
    ob[1] = make_float2(o2l, o0h);
    ob[2] = make_float2(o1h, o2h);
}

extern "C" void kernel_launch(void* const* d_in, const int* in_sizes, int n_in,
                              void* d_out, int out_size)
{
    const float* x = (const float*)d_in[0];   // (B, 3, 1)
    const float* c = (const float*)d_in[1];   // (B, 6)
    const float* G = (const float*)d_in[2];   // (6, 3, 3)
    float* out = (float*)d_out;               // (B, 3, 1)

    int pairs = B_TOTAL / 2;                  // 1048576 threads
    int grid = pairs / THREADS;               // 4096 blocks
    expm_apply_kernel<<<grid, THREADS>>>(x, c, G, out);
}

// round 13
// speedup vs baseline: 1.0871x; 1.0871x over previous
#include <cuda_runtime.h>
#include <cuda_bf16.h>

// dLDS_continuous: out[b] = expm(sum_m c[b,m] * G[m]) @ x[b]
// B = 2097152, N = 3, M = 6.
//
// Cayley-Hamilton coefficient-space expm, packed f32x2, 2 batches/thread.
// R12 (on the R10 base; R11's occupancy cap reverted — it spilled):
//  - c/x global loads hoisted ABOVE the sG setup + __syncthreads so DRAM
//    latency overlaps the barrier instead of stalling every warp after it
//  - scaling s=2 with deg-12 folded-constant Horner Taylor (10 iters):
//    one fewer 16-op squaring for three 3-op iterations (net -7 packed ops).
//    max ||T||_F ~ 7 (chi_6 tail over 2M) -> theta <= 1.75; deg-12 remainder
//    2.3e-7, x4 squaring amplification -> ~1e-6. Safe at the 1e-3 gate.
// out = a0*x + (a1/4)*y + (a2/16)*z with y = T x, z = T y.

static constexpr int B_TOTAL = 2097152;
static constexpr int THREADS = 256;

typedef unsigned long long u64;

__device__ __forceinline__ u64 pk(float a, float b) {
    u64 r; asm("mov.b64 %0, {%1,%2};" : "=l"(r) : "f"(a), "f"(b)); return r;
}
__device__ __forceinline__ void upk(u64 v, float& a, float& b) {
    asm("mov.b64 {%0,%1}, %2;" : "=f"(a), "=f"(b) : "l"(v));
}
__device__ __forceinline__ u64 f2fma(u64 a, u64 b, u64 c) {
    u64 r; asm("fma.rn.f32x2 %0, %1, %2, %3;" : "=l"(r) : "l"(a), "l"(b), "l"(c)); return r;
}
__device__ __forceinline__ u64 f2mul(u64 a, u64 b) {
    u64 r; asm("mul.rn.f32x2 %0, %1, %2;" : "=l"(r) : "l"(a), "l"(b)); return r;
}
__device__ __forceinline__ u64 f2add(u64 a, u64 b) {
    u64 r; asm("add.rn.f32x2 %0, %1, %2;" : "=l"(r) : "l"(a), "l"(b)); return r;
}
__device__ __forceinline__ u64 f2sub(u64 a, u64 b) {
    u64 r; asm("sub.rn.f32x2 %0, %1, %2;" : "=l"(r) : "l"(a), "l"(b)); return r;
}

__global__ void __launch_bounds__(THREADS)
expm_apply_kernel(const float* __restrict__ x,
                  const float* __restrict__ c,
                  const float* __restrict__ G,
                  float* __restrict__ out)
{
    // rows padded to 10 u64: 16B-aligned pairs -> ld.shared.v2.u64
    __shared__ alignas(16) u64 sG[60];
    int tid = threadIdx.x;
    unsigned t = blockIdx.x * THREADS + tid;   // pair index: batches 2t, 2t+1

    // ---- hoist per-thread global loads ABOVE sG setup + barrier:
    //      their DRAM latency overlaps the barrier wait ----
    const float4* c4 = reinterpret_cast<const float4*>(c) + t * 3u;
    float4 q0 = c4[0];
    float4 q1 = c4[1];
    float4 q2 = c4[2];
    const float2* x2 = reinterpret_cast<const float2*>(x) + t * 3u;
    float2 xa = x2[0];
    float2 xb = x2[1];
    float2 xc = x2[2];

    if (tid < 54) {
        int m = tid / 9, k = tid % 9;
        float g = G[tid];
        sG[m * 10 + k] = pk(g, g);
    }
    __syncthreads();

    u64 X0, X1, X2, Y0, Y1, Y2, Z0, Z1, Z2;
    u64 c0i, c1i, c2i;
    {
        u64 cc[6] = { pk(q0.x, q1.z), pk(q0.y, q1.w), pk(q0.z, q2.x),
                      pk(q0.w, q2.y), pk(q1.x, q2.z), pk(q1.y, q2.w) };

        // ---- T = sum_m c[m]*G[m]; G rows via 4x LDS.128 + 1x LDS.64 ----
        u64 A[9];
#pragma unroll
        for (int m = 0; m < 6; ++m) {
            const u64* row = &sG[m * 10];
            u64 cm = cc[m];
#pragma unroll
            for (int kp = 0; kp < 4; ++kp) {
                ulonglong2 g2 = *reinterpret_cast<const ulonglong2*>(row + 2 * kp);
                if (m == 0) {
                    A[2 * kp]     = f2mul(cm, g2.x);
                    A[2 * kp + 1] = f2mul(cm, g2.y);
                } else {
                    A[2 * kp]     = f2fma(cm, g2.x, A[2 * kp]);
                    A[2 * kp + 1] = f2fma(cm, g2.y, A[2 * kp + 1]);
                }
            }
            u64 g8 = row[8];
            if (m == 0) A[8] = f2mul(cm, g8);
            else        A[8] = f2fma(cm, g8, A[8]);
        }

        // ---- invariants of T ----
        u64 I1 = f2add(f2add(A[0], A[4]), A[8]);
        u64 m0 = f2sub(f2mul(A[4], A[8]), f2mul(A[5], A[7]));
        u64 m1 = f2sub(f2mul(A[0], A[8]), f2mul(A[2], A[6]));
        u64 m2 = f2sub(f2mul(A[0], A[4]), f2mul(A[1], A[3]));
        u64 I2 = f2add(f2add(m0, m1), m2);
        u64 u1 = f2sub(f2mul(A[3], A[8]), f2mul(A[5], A[6]));
        u64 u2 = f2sub(f2mul(A[3], A[7]), f2mul(A[4], A[6]));
        u64 I3 = f2fma(A[0], m0, f2sub(f2mul(A[2], u2), f2mul(A[1], u1)));

        // char poly of As = T/4:  As^3 = c0 I + c1 As + c2 As^2  (s = 2)
        const u64 SC1  = pk( 1.f / 4.f,   1.f / 4.f);
        const u64 SC2N = pk(-1.f / 16.f, -1.f / 16.f);
        const u64 SC3  = pk( 1.f / 64.f,  1.f / 64.f);
        c2i = f2mul(I1, SC1);
        c1i = f2mul(I2, SC2N);
        c0i = f2mul(I3, SC3);

        // ---- early matvecs: y = T x, z = T y (A dies here) ----
        X0 = pk(xa.x, xb.y);
        X1 = pk(xa.y, xc.x);
        X2 = pk(xb.x, xc.y);
        Y0 = f2fma(A[0], X0, f2fma(A[1], X1, f2mul(A[2], X2)));
        Y1 = f2fma(A[3], X0, f2fma(A[4], X1, f2mul(A[5], X2)));
        Y2 = f2fma(A[6], X0, f2fma(A[7], X1, f2mul(A[8], X2)));
        Z0 = f2fma(A[0], Y0, f2fma(A[1], Y1, f2mul(A[2], Y2)));
        Z1 = f2fma(A[3], Y0, f2fma(A[4], Y1, f2mul(A[5], Y2)));
        Z2 = f2fma(A[6], Y0, f2fma(A[7], Y1, f2mul(A[8], Y2)));
    }

    // ---- Taylor deg 12, folded-constant Horner in triple space ----
    // W_j = As*W_{j+1} + (12!/j!) I ; after two trivial iters W = (132, 12, 1).
    // Per iter: w0' = fma(w2,c0,M_j); w1' = fma(w2,c1,w0); w2' = fma(w2,c2,w1).
    u64 w0 = pk(132.f, 132.f);
    u64 w1 = pk(12.f, 12.f);
    u64 w2 = pk(1.f, 1.f);
    const float MJ[10] = { 1320.f, 11880.f, 95040.f, 665280.f, 3991680.f,
                           19958400.f, 79833600.f, 239500800.f,
                           479001600.f, 479001600.f };  // 12!/j!, j=9..0
#pragma unroll
    for (int k = 0; k < 10; ++k) {
        u64 Mj = pk(MJ[k], MJ[k]);
        u64 nw0 = f2fma(w2, c0i, Mj);
        u64 nw1 = f2fma(w2, c1i, w0);
        u64 nw2 = f2fma(w2, c2i, w1);
        w0 = nw0; w1 = nw1; w2 = nw2;
    }
    // normalize: E = W / 12!
    const u64 NRM = pk(1.f / 479001600.f, 1.f / 479001600.f);
    u64 a0 = f2mul(w0, NRM);
    u64 a1 = f2mul(w1, NRM);
    u64 a2 = f2mul(w2, NRM);

    // ---- As^4 reduction triple ----
    u64 d0 = f2mul(c2i, c0i);
    u64 d1 = f2fma(c2i, c1i, c0i);
    u64 d2 = f2fma(c2i, c2i, c1i);

    // ---- 2 squarings in coefficient space (s = 2) ----
#pragma unroll
    for (int it = 0; it < 2; ++it) {
        u64 q01 = f2mul(a0, a1);
        u64 q02 = f2mul(a0, a2);
        u64 q12 = f2mul(a1, a2);
        u64 q22 = f2mul(a2, a2);
        u64 t12 = f2add(q12, q12);
        u64 b0 = f2fma(q22, d0, f2fma(t12, c0i, f2mul(a0, a0)));
        u64 b1 = f2fma(q22, d1, f2fma(t12, c1i, f2add(q01, q01)));
        u64 b2 = f2fma(q22, d2, f2fma(t12, c2i, f2fma(a1, a1, f2add(q02, q02))));
        a0 = b0; a1 = b1; a2 = b2;
    }
    // fold 2^-2 / 2^-4 (y, z were computed with raw T)
    a1 = f2mul(a1, pk(1.f / 4.f,  1.f / 4.f));
    a2 = f2mul(a2, pk(1.f / 16.f, 1.f / 16.f));

    // ---- out = a0*x + a1*y + a2*z ----
    u64 O0 = f2fma(a0, X0, f2fma(a1, Y0, f2mul(a2, Z0)));
    u64 O1 = f2fma(a0, X1, f2fma(a1, Y1, f2mul(a2, Z1)));
    u64 O2 = f2fma(a0, X2, f2fma(a1, Y2, f2mul(a2, Z2)));

    float o0l, o0h, o1l, o1h, o2l, o2h;
    upk(O0, o0l, o0h);
    upk(O1, o1l, o1h);
    upk(O2, o2l, o2h);

    float2* ob = reinterpret_cast<float2*>(out) + t * 3u;
    ob[0] = make_float2(o0l, o1l);
    ob[1] = make_float2(o2l, o0h);
    ob[2] = make_float2(o1h, o2h);
}

extern "C" void kernel_launch(void* const* d_in, const int* in_sizes, int n_in,
                              void* d_out, int out_size)
{
    const float* x = (const float*)d_in[0];   // (B, 3, 1)
    const float* c = (const float*)d_in[1];   // (B, 6)
    const float* G = (const float*)d_in[2];   // (6, 3, 3)
    float* out = (float*)d_out;               // (B, 3, 1)

    int pairs = B_TOTAL / 2;                  // 1048576 threads
    int grid = pairs / THREADS;               // 4096 blocks
    expm_apply_kernel<<<grid, THREADS>>>(x, c, G, out);
}

// round 14
// speedup vs baseline: 1.0885x; 1.0013x over previous
#include <cuda_runtime.h>
#include <cuda_bf16.h>

// dLDS_continuous: out[b] = expm(sum_m c[b,m] * G[m]) @ x[b]
// B = 2097152, N = 3, M = 6.
//
// Cayley-Hamilton coefficient-space expm, packed f32x2, 2 batches/thread,
// s=2 + deg-12 folded-constant Horner Taylor (R12 algorithm, unchanged).
// R13: all packed f32x2 constants live in __constant__ memory and are loaded
// as 64-bit LDC instead of being materialized with MOV32I pairs on the alu
// pipe (each inline-asm pk() was an un-CSE-able MOV64). ~38 alu issue slots
// -> ~18 constant-port loads, freeing issue bandwidth for the FFMA2 stream.

static constexpr int B_TOTAL = 2097152;
static constexpr int THREADS = 256;

typedef unsigned long long u64;

// packed constants, both lanes equal; indexed as u64
// 0:SC1(1/4)  1:SC2N(-1/16)  2:SC3(1/64)  3:FOLD2(1/16)  4:NRM(1/12!)
// 5:W0(132)   6:W1(12)       7:ONE(1)     8..17: MJ = 12!/j!, j=9..0
__constant__ float2 KC[18] = {
    {0.25f, 0.25f},
    {-0.0625f, -0.0625f},
    {0.015625f, 0.015625f},
    {0.0625f, 0.0625f},
    {1.f / 479001600.f, 1.f / 479001600.f},
    {132.f, 132.f},
    {12.f, 12.f},
    {1.f, 1.f},
    {1320.f, 1320.f},
    {11880.f, 11880.f},
    {95040.f, 95040.f},
    {665280.f, 665280.f},
    {3991680.f, 3991680.f},
    {19958400.f, 19958400.f},
    {79833600.f, 79833600.f},
    {239500800.f, 239500800.f},
    {479001600.f, 479001600.f},
    {479001600.f, 479001600.f},
};

__device__ __forceinline__ u64 pk(float a, float b) {
    u64 r; asm("mov.b64 %0, {%1,%2};" : "=l"(r) : "f"(a), "f"(b)); return r;
}
__device__ __forceinline__ void upk(u64 v, float& a, float& b) {
    asm("mov.b64 {%0,%1}, %2;" : "=f"(a), "=f"(b) : "l"(v));
}
__device__ __forceinline__ u64 f2fma(u64 a, u64 b, u64 c) {
    u64 r; asm("fma.rn.f32x2 %0, %1, %2, %3;" : "=l"(r) : "l"(a), "l"(b), "l"(c)); return r;
}
__device__ __forceinline__ u64 f2mul(u64 a, u64 b) {
    u64 r; asm("mul.rn.f32x2 %0, %1, %2;" : "=l"(r) : "l"(a), "l"(b)); return r;
}
__device__ __forceinline__ u64 f2add(u64 a, u64 b) {
    u64 r; asm("add.rn.f32x2 %0, %1, %2;" : "=l"(r) : "l"(a), "l"(b)); return r;
}
__device__ __forceinline__ u64 f2sub(u64 a, u64 b) {
    u64 r; asm("sub.rn.f32x2 %0, %1, %2;" : "=l"(r) : "l"(a), "l"(b)); return r;
}

__global__ void __launch_bounds__(THREADS)
expm_apply_kernel(const float* __restrict__ x,
                  const float* __restrict__ c,
                  const float* __restrict__ G,
                  float* __restrict__ out)
{
    const u64* kc = reinterpret_cast<const u64*>(KC);

    // rows padded to 10 u64: 16B-aligned pairs -> ld.shared.v2.u64
    __shared__ alignas(16) u64 sG[60];
    int tid = threadIdx.x;
    unsigned t = blockIdx.x * THREADS + tid;   // pair index: batches 2t, 2t+1

    // ---- per-thread global loads hoisted above barrier (overlap latency) ----
    const float4* c4 = reinterpret_cast<const float4*>(c) + t * 3u;
    float4 q0 = c4[0];
    float4 q1 = c4[1];
    float4 q2 = c4[2];
    const float2* x2 = reinterpret_cast<const float2*>(x) + t * 3u;
    float2 xa = x2[0];
    float2 xb = x2[1];
    float2 xc = x2[2];

    if (tid < 54) {
        int m = tid / 9, k = tid % 9;
        float g = G[tid];
        sG[m * 10 + k] = pk(g, g);
    }
    __syncthreads();

    u64 X0, X1, X2, Y0, Y1, Y2, Z0, Z1, Z2;
    u64 c0i, c1i, c2i;
    {
        u64 cc[6] = { pk(q0.x, q1.z), pk(q0.y, q1.w), pk(q0.z, q2.x),
                      pk(q0.w, q2.y), pk(q1.x, q2.z), pk(q1.y, q2.w) };

        // ---- T = sum_m c[m]*G[m]; G rows via 4x LDS.128 + 1x LDS.64 ----
        u64 A[9];
#pragma unroll
        for (int m = 0; m < 6; ++m) {
            const u64* row = &sG[m * 10];
            u64 cm = cc[m];
#pragma unroll
            for (int kp = 0; kp < 4; ++kp) {
                ulonglong2 g2 = *reinterpret_cast<const ulonglong2*>(row + 2 * kp);
                if (m == 0) {
                    A[2 * kp]     = f2mul(cm, g2.x);
                    A[2 * kp + 1] = f2mul(cm, g2.y);
                } else {
                    A[2 * kp]     = f2fma(cm, g2.x, A[2 * kp]);
                    A[2 * kp + 1] = f2fma(cm, g2.y, A[2 * kp + 1]);
                }
            }
            u64 g8 = row[8];
            if (m == 0) A[8] = f2mul(cm, g8);
            else        A[8] = f2fma(cm, g8, A[8]);
        }

        // ---- invariants of T ----
        u64 I1 = f2add(f2add(A[0], A[4]), A[8]);
        u64 m0 = f2sub(f2mul(A[4], A[8]), f2mul(A[5], A[7]));
        u64 m1 = f2sub(f2mul(A[0], A[8]), f2mul(A[2], A[6]));
        u64 m2 = f2sub(f2mul(A[0], A[4]), f2mul(A[1], A[3]));
        u64 I2 = f2add(f2add(m0, m1), m2);
        u64 u1 = f2sub(f2mul(A[3], A[8]), f2mul(A[5], A[6]));
        u64 u2 = f2sub(f2mul(A[3], A[7]), f2mul(A[4], A[6]));
        u64 I3 = f2fma(A[0], m0, f2sub(f2mul(A[2], u2), f2mul(A[1], u1)));

        // char poly of As = T/4:  As^3 = c0 I + c1 As + c2 As^2  (s = 2)
        c2i = f2mul(I1, kc[0]);    // * 1/4
        c1i = f2mul(I2, kc[1]);    // * -1/16
        c0i = f2mul(I3, kc[2]);    // * 1/64

        // ---- early matvecs: y = T x, z = T y (A dies here) ----
        X0 = pk(xa.x, xb.y);
        X1 = pk(xa.y, xc.x);
        X2 = pk(xb.x, xc.y);
        Y0 = f2fma(A[0], X0, f2fma(A[1], X1, f2mul(A[2], X2)));
        Y1 = f2fma(A[3], X0, f2fma(A[4], X1, f2mul(A[5], X2)));
        Y2 = f2fma(A[6], X0, f2fma(A[7], X1, f2mul(A[8], X2)));
        Z0 = f2fma(A[0], Y0, f2fma(A[1], Y1, f2mul(A[2], Y2)));
        Z1 = f2fma(A[3], Y0, f2fma(A[4], Y1, f2mul(A[5], Y2)));
        Z2 = f2fma(A[6], Y0, f2fma(A[7], Y1, f2mul(A[8], Y2)));
    }

    // ---- Taylor deg 12, folded-constant Horner in triple space ----
    // W_j = As*W_{j+1} + (12!/j!) I ; after two trivial iters W = (132, 12, 1).
    u64 w0 = kc[5];
    u64 w1 = kc[6];
    u64 w2 = kc[7];
#pragma unroll
    for (int k = 0; k < 10; ++k) {
        u64 Mj = kc[8 + k];
        u64 nw0 = f2fma(w2, c0i, Mj);
        u64 nw1 = f2fma(w2, c1i, w0);
        u64 nw2 = f2fma(w2, c2i, w1);
        w0 = nw0; w1 = nw1; w2 = nw2;
    }
    // normalize: E = W / 12!
    u64 a0 = f2mul(w0, kc[4]);
    u64 a1 = f2mul(w1, kc[4]);
    u64 a2 = f2mul(w2, kc[4]);

    // ---- As^4 reduction triple ----
    u64 d0 = f2mul(c2i, c0i);
    u64 d1 = f2fma(c2i, c1i, c0i);
    u64 d2 = f2fma(c2i, c2i, c1i);

    // ---- 2 squarings in coefficient space (s = 2) ----
#pragma unroll
    for (int it = 0; it < 2; ++it) {
        u64 q01 = f2mul(a0, a1);
        u64 q02 = f2mul(a0, a2);
        u64 q12 = f2mul(a1, a2);
        u64 q22 = f2mul(a2, a2);
        u64 t12 = f2add(q12, q12);
        u64 b0 = f2fma(q22, d0, f2fma(t12, c0i, f2mul(a0, a0)));
        u64 b1 = f2fma(q22, d1, f2fma(t12, c1i, f2add(q01, q01)));
        u64 b2 = f2fma(q22, d2, f2fma(t12, c2i, f2fma(a1, a1, f2add(q02, q02))));
        a0 = b0; a1 = b1; a2 = b2;
    }
    // fold 2^-2 / 2^-4 (y, z were computed with raw T)
    a1 = f2mul(a1, kc[0]);   // * 1/4
    a2 = f2mul(a2, kc[3]);   // * 1/16

    // ---- out = a0*x + a1*y + a2*z ----
    u64 O0 = f2fma(a0, X0, f2fma(a1, Y0, f2mul(a2, Z0)));
    u64 O1 = f2fma(a0, X1, f2fma(a1, Y1, f2mul(a2, Z1)));
    u64 O2 = f2fma(a0, X2, f2fma(a1, Y2, f2mul(a2, Z2)));

    float o0l, o0h, o1l, o1h, o2l, o2h;
    upk(O0, o0l, o0h);
    upk(O1, o1l, o1h);
    upk(O2, o2l, o2h);

    float2* ob = reinterpret_cast<float2*>(out) + t * 3u;
    ob[0] = make_float2(o0l, o1l);
    ob[1] = make_float2(o2l, o0h);
    ob[2] = make_float2(o1h, o2h);
}

extern "C" void kernel_launch(void* const* d_in, const int* in_sizes, int n_in,
                              void* d_out, int out_size)
{
    const float* x = (const float*)d_in[0];   // (B, 3, 1)
    const float* c = (const float*)d_in[1];   // (B, 6)
    const float* G = (const float*)d_in[2];   // (6, 3, 3)
    float* out = (float*)d_out;               // (B, 3, 1)

    int pairs = B_TOTAL / 2;                  // 1048576 threads
    int grid = pairs / THREADS;               // 4096 blocks
    expm_apply_kernel<<<grid, THREADS>>>(x, c, G, out);
}